// round 2
// baseline (speedup 1.0000x reference)
#include <cuda_runtime.h>

// ---------------- problem constants ----------------
#define NNODES 4096          // B*n
#define NBATCH 64
#define NPG    64            // nodes per graph
#define HD     128
#define HD4    32            // HD/4
#define NE     131072        // B*epg edges (before self loops)
#define KK     52            // ceil(0.8*64)
#define NK     3328          // B*KK

#define LEN_X  (NK*HD)                    // 425984
#define OFF_A2 (LEN_X)
#define OFF_B  (OFF_A2 + NK*NK)           // 11501568
#define OFF_P  (OFF_B + NK)               // 11504896

#define BM 128
#define BN 128
#define BK 16

// ---------------- scratch (device globals; no allocation) ----------------
__device__ float g_deg[NNODES];
__device__ float g_dinv[NNODES];
__device__ float g_A[NBATCH*NPG*NPG];     // dense per-batch normalized adjacency (row,col)
__device__ float g_Cnt[NBATCH*NPG*NPG];   // edge multiplicity
__device__ float g_S[NBATCH*NPG*NPG];     // E_g dense per-batch
__device__ float g_tmp[NNODES*HD];
__device__ float g_xq[NNODES*HD];
__device__ float g_qt[NNODES*HD];
__device__ float g_a[2*NNODES*HD];
__device__ float g_h1[2*NNODES*2*HD];
__device__ float g_h2[2*NNODES*HD];
__device__ float g_logit[2*NNODES];
__device__ float g_f[2*NNODES];
__device__ float g_agg[NNODES*HD];
__device__ float g_P[2*NNODES*HD];
__device__ float g_xc[NNODES*HD];
__device__ float g_score[NNODES];
__device__ int   g_perm[NK];

__device__ __forceinline__ float lrelu(float v){ return v > 0.f ? v : 0.01f*v; }

// f32x2 packed helpers (IEEE fp32 per lane — bit-identical to scalar FFMA)
__device__ __forceinline__ void fma2(unsigned long long& c, unsigned long long a, unsigned long long b){
    asm("fma.rn.f32x2 %0, %1, %2, %0;" : "+l"(c) : "l"(a), "l"(b));
}
__device__ __forceinline__ float2 u2f(unsigned long long v){
    float2 r; asm("mov.b64 {%0,%1}, %2;" : "=f"(r.x), "=f"(r.y) : "l"(v)); return r;
}

// ---------------- setup kernels ----------------
__global__ void k_init(){
    int i = blockIdx.x*blockDim.x + threadIdx.x;
    if (i < NBATCH*NPG*NPG){ g_A[i]=0.f; g_Cnt[i]=0.f; }
    if (i < NNODES) g_deg[i] = 1.0f;     // self-loop weight
}

__global__ void k_deg(const int* __restrict__ col, const float* __restrict__ w){
    int e = blockIdx.x*blockDim.x + threadIdx.x;
    if (e < NE) atomicAdd(&g_deg[col[e]], w[e]);
}

__global__ void k_dinv(){
    int i = blockIdx.x*blockDim.x + threadIdx.x;
    if (i < NNODES) g_dinv[i] = rsqrtf(g_deg[i]);
}

__global__ void k_build(const int* __restrict__ row, const int* __restrict__ col,
                        const float* __restrict__ w){
    int e = blockIdx.x*blockDim.x + threadIdx.x;
    if (e < NE){
        int r = row[e], c = col[e];
        float ew = g_dinv[r]*w[e]*g_dinv[c];
        int b = r >> 6;
        int idx = b*NPG*NPG + (r&63)*NPG + (c&63);
        atomicAdd(&g_A[idx], ew);
        atomicAdd(&g_Cnt[idx], 1.0f);
    } else if (e < NE + NNODES){
        int i = e - NE;
        int b = i >> 6, l = i & 63;
        int idx = b*NPG*NPG + l*NPG + l;
        atomicAdd(&g_A[idx], g_dinv[i]*g_dinv[i]);
        atomicAdd(&g_Cnt[idx], 1.0f);
    }
}

__global__ void k_qt(const float4* __restrict__ tx4){
    int i = blockIdx.x*blockDim.x + threadIdx.x;   // < NNODES*HD4
    int node = i >> 5, f4 = i & 31;
    ((float4*)g_qt)[i] = tx4[(node>>6)*HD4 + f4];
}

// hop: out[c] = sum_r A[r][c] * v[r]  (per-batch dense)
__global__ void k_hop(const float4* __restrict__ vin, float4* __restrict__ vout){
    int b = blockIdx.x, t = threadIdx.x;
    __shared__ float sA[NPG*NPG];
    for (int i=t; i<NPG*NPG; i+=256) sA[i] = g_A[b*NPG*NPG+i];
    __syncthreads();
    int tx = t & 31, ty = t >> 5;
    for (int cc=0; cc<8; cc++){
        int c = ty*8+cc;
        float4 acc = make_float4(0.f,0.f,0.f,0.f);
        for (int r=0; r<NPG; r++){
            float a = sA[r*NPG+c];
            float4 v = vin[(b*NPG+r)*HD4 + tx];
            acc.x += a*v.x; acc.y += a*v.y; acc.z += a*v.z; acc.w += a*v.w;
        }
        vout[(b*NPG+c)*HD4 + tx] = acc;
    }
}

// ---------------- SGEMM: C = act(A @ B), 128x128 tile, 8x8/thread, f32x2 ----------------
// FUSE=1: A-tile is the on-the-fly concat [a, q, a-q, a*q] (K=512); A arg = g_a base.
template<int ACT, int FUSE>
__device__ __forceinline__ void gloadA(const float* __restrict__ A, const float* __restrict__ Q,
                                       int z, int rowBase, int ar, int akq, int K, int k0,
                                       float4& v0, float4& v1)
{
    if (FUSE){
        int k = k0 + akq;
        int sec = k >> 7, f = k & 127;
        const float* ap = A + ((size_t)(z*NNODES + rowBase + ar))*HD + f;
        const float* qp = Q + ((size_t)(rowBase + ar))*HD + f;
        if (sec == 0){ v0 = *(const float4*)ap; v1 = *(const float4*)(ap+4); }
        else if (sec == 1){ v0 = *(const float4*)qp; v1 = *(const float4*)(qp+4); }
        else {
            float4 a0 = *(const float4*)ap, a1 = *(const float4*)(ap+4);
            float4 q0v = *(const float4*)qp, q1v = *(const float4*)(qp+4);
            if (sec == 2){
                v0 = make_float4(a0.x-q0v.x, a0.y-q0v.y, a0.z-q0v.z, a0.w-q0v.w);
                v1 = make_float4(a1.x-q1v.x, a1.y-q1v.y, a1.z-q1v.z, a1.w-q1v.w);
            } else {
                v0 = make_float4(a0.x*q0v.x, a0.y*q0v.y, a0.z*q0v.z, a0.w*q0v.w);
                v1 = make_float4(a1.x*q1v.x, a1.y*q1v.y, a1.z*q1v.z, a1.w*q1v.w);
            }
        }
    } else {
        const float* p = A + (size_t)(rowBase + ar)*K + k0 + akq;
        v0 = *(const float4*)p; v1 = *(const float4*)(p+4);
    }
}

__device__ __forceinline__ void sstoreA(float* Ad, int ar, int akq, float4 v0, float4 v1){
    float2* d = (float2*)Ad;
    d[(akq+0)*BM + ar] = make_float2(v0.x, v0.x);
    d[(akq+1)*BM + ar] = make_float2(v0.y, v0.y);
    d[(akq+2)*BM + ar] = make_float2(v0.z, v0.z);
    d[(akq+3)*BM + ar] = make_float2(v0.w, v0.w);
    d[(akq+4)*BM + ar] = make_float2(v1.x, v1.x);
    d[(akq+5)*BM + ar] = make_float2(v1.y, v1.y);
    d[(akq+6)*BM + ar] = make_float2(v1.z, v1.z);
    d[(akq+7)*BM + ar] = make_float2(v1.w, v1.w);
}

template<int ACT, int FUSE>
__global__ void __launch_bounds__(256, 2) k_gemm(
    const float* __restrict__ A, const float* __restrict__ B, float* __restrict__ C,
    int M, int N, int K, long long sA, long long sB, long long sC,
    const float* __restrict__ q0, const float* __restrict__ q1)
{
    __shared__ float Ad[BK*BM*2];   // duplicated pairs {v,v}
    __shared__ float Bs[BK*BN];
    int z = blockIdx.z;
    if (!FUSE) A += (long long)z * sA;
    B += (long long)z * sB;
    C += (long long)z * sC;
    const float* Q = FUSE ? (z ? q1 : q0) : A;

    int t = threadIdx.x;
    int tx = t & 15, ty = t >> 4;
    int rowBase = blockIdx.y*BM, colBase = blockIdx.x*BN;
    int ar = t >> 1, akq = (t & 1)*8;
    int bk = t >> 4, bc = (t & 15)*8;

    unsigned long long acc[8][4];
#pragma unroll
    for (int i=0;i<8;i++)
#pragma unroll
        for (int j=0;j<4;j++) acc[i][j] = 0ULL;

    float4 ra0, ra1, rb0, rb1;
    gloadA<ACT,FUSE>(A, Q, z, rowBase, ar, akq, K, 0, ra0, ra1);
    {
        const float* p = B + (size_t)bk*N + colBase + bc;
        rb0 = *(const float4*)p; rb1 = *(const float4*)(p+4);
    }
    sstoreA(Ad, ar, akq, ra0, ra1);
    *(float4*)(Bs + bk*BN + bc)     = rb0;
    *(float4*)(Bs + bk*BN + bc + 4) = rb1;
    __syncthreads();

    for (int k0 = 0; k0 < K; k0 += BK){
        bool more = (k0 + BK) < K;
        if (more){
            gloadA<ACT,FUSE>(A, Q, z, rowBase, ar, akq, K, k0+BK, ra0, ra1);
            const float* p = B + (size_t)(k0+BK+bk)*N + colBase + bc;
            rb0 = *(const float4*)p; rb1 = *(const float4*)(p+4);
        }
#pragma unroll
        for (int kk=0; kk<BK; kk++){
            const ulonglong2* Au = (const ulonglong2*)(Ad + 2*(kk*BM + ty*8));
            ulonglong2 a01 = Au[0], a23 = Au[1], a45 = Au[2], a67 = Au[3];
            const ulonglong2* Bu = (const ulonglong2*)(Bs + kk*BN + tx*8);
            ulonglong2 b01 = Bu[0], b23 = Bu[1];
            unsigned long long am[8] = {a01.x, a01.y, a23.x, a23.y, a45.x, a45.y, a67.x, a67.y};
            unsigned long long bn[4] = {b01.x, b01.y, b23.x, b23.y};
#pragma unroll
            for (int i=0;i<8;i++)
#pragma unroll
                for (int j=0;j<4;j++) fma2(acc[i][j], am[i], bn[j]);
        }
        __syncthreads();
        if (more){
            sstoreA(Ad, ar, akq, ra0, ra1);
            *(float4*)(Bs + bk*BN + bc)     = rb0;
            *(float4*)(Bs + bk*BN + bc + 4) = rb1;
            __syncthreads();
        }
    }

#pragma unroll
    for (int i=0;i<8;i++){
        float2 c0 = u2f(acc[i][0]), c1 = u2f(acc[i][1]), c2 = u2f(acc[i][2]), c3 = u2f(acc[i][3]);
        if (ACT){
            c0.x=lrelu(c0.x); c0.y=lrelu(c0.y); c1.x=lrelu(c1.x); c1.y=lrelu(c1.y);
            c2.x=lrelu(c2.x); c2.y=lrelu(c2.y); c3.x=lrelu(c3.x); c3.y=lrelu(c3.y);
        }
        float* cp = C + (size_t)(rowBase + ty*8 + i)*N + colBase + tx*8;
        *(float4*)cp     = make_float4(c0.x, c0.y, c1.x, c1.y);
        *(float4*)(cp+4) = make_float4(c2.x, c2.y, c3.x, c3.y);
    }
}

// ---------------- attention helpers ----------------
__global__ void k_w3(const float* __restrict__ W3, int base){
    int gt = blockIdx.x*blockDim.x + threadIdx.x;
    int warp = gt >> 5, lane = gt & 31;
    if (warp >= 2*NNODES) return;
    int z = warp >> 12;
    const float* w = W3 + (size_t)(base+z)*HD;
    const float* h = g_h2 + (size_t)warp*HD;
    float s = 0.f;
#pragma unroll
    for (int k=0; k<4; k++) s += h[lane+32*k]*w[lane+32*k];
    for (int o=16; o; o>>=1) s += __shfl_xor_sync(0xffffffffu, s, o);
    if (lane == 0) g_logit[warp] = lrelu(s);
}

__global__ void k_softmax64(const float* __restrict__ in, float* __restrict__ out){
    __shared__ float red[64];
    int b = blockIdx.x, t = threadIdx.x;
    float v = in[b*64+t];
    red[t] = v; __syncthreads();
    for (int o=32; o>0; o>>=1){ if (t<o) red[t] = fmaxf(red[t], red[t+o]); __syncthreads(); }
    float m = red[0];
    __syncthreads();
    float e = expf(v - m);
    red[t] = e; __syncthreads();
    for (int o=32; o>0; o>>=1){ if (t<o) red[t] += red[t+o]; __syncthreads(); }
    out[b*64+t] = e / red[0];
}

// cluster score: softmax over (f1+f2) per batch
__global__ void k_score(){
    __shared__ float red[64];
    int b = blockIdx.x, t = threadIdx.x;
    float v = g_f[b*64+t] + g_f[NNODES + b*64+t];
    red[t] = v; __syncthreads();
    for (int o=32; o>0; o>>=1){ if (t<o) red[t] = fmaxf(red[t], red[t+o]); __syncthreads(); }
    float m = red[0];
    __syncthreads();
    float e = expf(v - m);
    red[t] = e; __syncthreads();
    for (int o=32; o>0; o>>=1){ if (t<o) red[t] += red[t+o]; __syncthreads(); }
    g_score[b*64+t] = e / red[0];
}

// ---------------- edge softmax + S + agg (per-batch dense) ----------------
__global__ void k_edge(const float* __restrict__ x){
    int b = blockIdx.x, t = threadIdx.x;
    __shared__ float sC[NPG*NPG];
    __shared__ float sL[NPG*NPG];
    __shared__ float sf1[NPG], sf2[NPG], sm[NPG], sden[NPG];
    for (int i=t; i<NPG*NPG; i+=256) sC[i] = g_Cnt[b*NPG*NPG+i];
    if (t < NPG){ sf1[t] = g_f[b*NPG+t]; sf2[t] = g_f[NNODES + b*NPG+t]; }
    __syncthreads();
    for (int i=t; i<NPG*NPG; i+=256){
        int r = i>>6, c = i&63;
        sL[i] = (sC[i] > 0.f) ? lrelu(sf1[c] + sf2[r]) : -1e30f;
    }
    __syncthreads();
    if (t < NPG){
        float m = -1e30f;
        for (int r=0; r<NPG; r++) m = fmaxf(m, sL[r*NPG+t]);
        float den = 0.f;
        for (int r=0; r<NPG; r++){
            float cc = sC[r*NPG+t];
            if (cc > 0.f) den += cc*expf(sL[r*NPG+t]-m);
        }
        sm[t] = m; sden[t] = den;
    }
    __syncthreads();
    for (int i=t; i<NPG*NPG; i+=256){
        int c = i & 63;
        float cc = sC[i];
        float s = (cc > 0.f) ? cc*expf(sL[i]-sm[c])/sden[c] : 0.f;
        sL[i] = s;
        g_S[b*NPG*NPG+i] = s;
    }
    __syncthreads();
    const float4* X4 = (const float4*)x;
    float4* AG4 = (float4*)g_agg;
    int tx = t & 31, ty = t >> 5;
    for (int cc=0; cc<8; cc++){
        int c = ty*8+cc;
        float4 acc = make_float4(0.f,0.f,0.f,0.f);
        for (int r=0; r<NPG; r++){
            float s = sL[r*NPG+c];
            float4 v = X4[(b*NPG+r)*HD4 + tx];
            acc.x += s*v.x; acc.y += s*v.y; acc.z += s*v.z; acc.w += s*v.w;
        }
        AG4[(b*NPG+c)*HD4 + tx] = acc;
    }
}

__global__ void k_xc(const float* __restrict__ x){
    int i = blockIdx.x*blockDim.x + threadIdx.x;
    if (i < NNODES*HD){
        float xv = x[i];
        float v0 = lrelu(xv + g_P[i]);
        float v1 = lrelu(xv + g_P[NNODES*HD + i]);
        g_xc[i] = 0.5f*(v0+v1);
    }
}

// ---------------- top-k (stable, descending) + x_out/batch/perm outputs ----------------
__global__ void k_topk_out(const float* __restrict__ x, float* __restrict__ out){
    __shared__ float s[64];
    __shared__ int lp[KK];
    int b = blockIdx.x, t = threadIdx.x;   // 256 threads
    if (t < 64) s[t] = g_score[b*64+t];
    __syncthreads();
    if (t < 64){
        float v = s[t];
        int rank = 0;
        for (int j=0; j<64; j++){
            float u = s[j];
            rank += (u > v) || (u == v && j < t);
        }
        if (rank < KK){
            lp[rank] = t;
            g_perm[b*KK+rank] = b*64+t;
            out[OFF_B + b*KK+rank] = (float)b;
            out[OFF_P + b*KK+rank] = (float)(b*64+t);
        }
    }
    __syncthreads();
    const float4* x4 = (const float4*)x;
    float4* o4 = (float4*)out;
    for (int i=t; i<KK*32; i+=256){
        int r = i >> 5, f = i & 31;
        int p = lp[r];
        float sc = s[p];
        float4 v = x4[(b*64+p)*32 + f];
        o4[(size_t)(b*KK+r)*32 + f] = make_float4(v.x*sc, v.y*sc, v.z*sc, v.w*sc);
    }
}

// ---------------- A2 block triple-product ----------------
__global__ void k_A2(float* __restrict__ out){
    int b = blockIdx.x, t = threadIdx.x;
    __shared__ float sA[NPG*NPG];
    __shared__ float sS[NPG*NPG];
    __shared__ float sU[NPG*KK];
    __shared__ int   sI[KK];
    for (int i=t; i<NPG*NPG; i+=256){ sA[i] = g_A[b*NPG*NPG+i]; sS[i] = g_S[b*NPG*NPG+i]; }
    if (t < KK) sI[t] = g_perm[b*KK+t] - b*NPG;
    __syncthreads();
    // U[r][j] = sum_c A[r][c] * S[c][pj]
    for (int idx=t; idx<NPG*KK; idx+=256){
        int r = idx / KK, j = idx - r*KK;
        int pj = sI[j];
        float acc = 0.f;
        for (int c=0; c<NPG; c++) acc += sA[r*NPG+c]*sS[c*NPG+pj];
        sU[idx] = acc;
    }
    __syncthreads();
    // V[i][j] = sum_r S[r][pi] * U[r][j]; diag -> 1
    for (int idx=t; idx<KK*KK; idx+=256){
        int i2 = idx / KK, j = idx - i2*KK;
        int pi = sI[i2];
        float acc = 0.f;
        for (int r=0; r<NPG; r++) acc += sS[r*NPG+pi]*sU[r*KK+j];
        float v = (i2 == j) ? 1.0f : acc;
        out[(size_t)OFF_A2 + (size_t)(b*KK+i2)*NK + (b*KK+j)] = v;
    }
}

// ---------------- host-side attention pipeline ----------------
static void launch_attention(int base, const float* kv, const float* q0, const float* q1,
                             const float* Wk, const float* W1, const float* W2, const float* W3,
                             float* p_a, float* p_h1, float* p_h2,
                             float* p_logit, float* p_f)
{
    // a = kv @ Wk[base+z]
    k_gemm<0,0><<<dim3(1,32,2),256>>>(kv, Wk + (long long)base*HD*HD, p_a,
                                      NNODES, HD, HD,
                                      0LL, (long long)HD*HD, (long long)NNODES*HD,
                                      nullptr, nullptr);
    // h1 = lrelu(concat[a,q,a-q,a*q] @ W1[base+z])  (concat fused into A-tile loader)
    k_gemm<1,1><<<dim3(2,32,2),256>>>(p_a, W1 + (long long)base*512*256, p_h1,
                                      NNODES, 256, 512,
                                      0LL, 512LL*256, (long long)NNODES*256,
                                      q0, q1);
    // h2 = lrelu(h1 @ W2[base+z])
    k_gemm<1,0><<<dim3(1,32,2),256>>>(p_h1, W2 + (long long)base*256*128, p_h2,
                                      NNODES, 128, 256,
                                      (long long)NNODES*256, 256LL*128, (long long)NNODES*128,
                                      nullptr, nullptr);
    k_w3<<<(2*NNODES*32)/256,256>>>(W3, base);
    k_softmax64<<<2*NBATCH,64>>>(p_logit, p_f);
}

extern "C" void kernel_launch(void* const* d_in, const int* in_sizes, int n_in,
                              void* d_out, int out_size)
{
    (void)in_sizes; (void)n_in; (void)out_size;
    const float* x    = (const float*)d_in[0];
    const int*   ei   = (const int*)  d_in[1];
    const float* ew   = (const float*)d_in[2];
    const float* txg  = (const float*)d_in[3];
    const float* Wk   = (const float*)d_in[5];
    const float* W1   = (const float*)d_in[6];
    const float* W2   = (const float*)d_in[7];
    const float* W3   = (const float*)d_in[8];
    const float* linW = (const float*)d_in[9];
    float* out = (float*)d_out;
    const int* row = ei;
    const int* col = ei + NE;

    float *p_tmp,*p_xq,*p_qt,*p_a,*p_h1,*p_h2,*p_logit,*p_f,*p_agg,*p_P,*p_xc;
    cudaGetSymbolAddress((void**)&p_tmp,   g_tmp);
    cudaGetSymbolAddress((void**)&p_xq,    g_xq);
    cudaGetSymbolAddress((void**)&p_qt,    g_qt);
    cudaGetSymbolAddress((void**)&p_a,     g_a);
    cudaGetSymbolAddress((void**)&p_h1,    g_h1);
    cudaGetSymbolAddress((void**)&p_h2,    g_h2);
    cudaGetSymbolAddress((void**)&p_logit, g_logit);
    cudaGetSymbolAddress((void**)&p_f,     g_f);
    cudaGetSymbolAddress((void**)&p_agg,   g_agg);
    cudaGetSymbolAddress((void**)&p_P,     g_P);
    cudaGetSymbolAddress((void**)&p_xc,    g_xc);

    // graph setup
    k_init<<<1024,256>>>();
    k_deg<<<NE/256,256>>>(col, ew);
    k_dinv<<<NNODES/256,256>>>();
    k_build<<<(NE+NNODES)/256,256>>>(row, col, ew);
    k_qt<<<(NNODES*HD4)/256,256>>>((const float4*)txg);

    // x_q = hop(hop(x))
    k_hop<<<NBATCH,256>>>((const float4*)x, (float4*)p_tmp);
    k_hop<<<NBATCH,256>>>((const float4*)p_tmp, (float4*)p_xq);

    // f1 = att(x, x_q, W[0]); f2 = att(x, qt, W[1])
    launch_attention(0, x, p_xq, p_qt, Wk, W1, W2, W3, p_a, p_h1, p_h2, p_logit, p_f);

    // edge softmax -> S, agg
    k_edge<<<NBATCH,256>>>(x);

    // x_c = mean_h lrelu(x + agg @ lin_W[h])
    k_gemm<0,0><<<dim3(1,32,2),256>>>(p_agg, linW, p_P, NNODES, HD, HD,
                                      0LL, (long long)HD*HD, (long long)NNODES*HD,
                                      nullptr, nullptr);
    k_xc<<<(NNODES*HD)/256,256>>>(x);

    // x_q2 = hop(hop(x_c))
    k_hop<<<NBATCH,256>>>((const float4*)p_xc, (float4*)p_tmp);
    k_hop<<<NBATCH,256>>>((const float4*)p_tmp, (float4*)p_xq);

    // g1 = att(x_c, x_q2, W[2]); g2 = att(x_c, qt, W[3])
    launch_attention(2, p_xc, p_xq, p_qt, Wk, W1, W2, W3, p_a, p_h1, p_h2, p_logit, p_f);

    // cluster_score = softmax_batch(g1+g2)
    k_score<<<NBATCH,64>>>();

    // top-k + x_out/batch/perm outputs
    k_topk_out<<<NBATCH,256>>>(x, out);
    cudaMemsetAsync(out + OFF_A2, 0, (size_t)NK*NK*sizeof(float));
    k_A2<<<NBATCH,256>>>(out);
}